// round 2
// baseline (speedup 1.0000x reference)
#include <cuda_runtime.h>
#include <math.h>

#define N_NODES 25000
#define N_EDGES 200000
#define HID     128
#define N_GRAPHS 64
#define DEPTH   5
#define NODE_F  16

// Scratch (static device globals; no allocation allowed)
__device__ float g_h[N_NODES * HID];
__device__ float g_agg[N_NODES * HID];
__device__ float g_dist[N_EDGES];
__device__ float g_pool[N_GRAPHS * HID];

// ---------------------------------------------------------------------------
__global__ void dist_kernel(const float* __restrict__ pos, const int* __restrict__ ei) {
    int e = blockIdx.x * blockDim.x + threadIdx.x;
    if (e >= N_EDGES) return;
    int s = ei[e];
    int d = ei[N_EDGES + e];
    float dx = pos[d * 3 + 0] - pos[s * 3 + 0];
    float dy = pos[d * 3 + 1] - pos[s * 3 + 1];
    float dz = pos[d * 3 + 2] - pos[s * 3 + 2];
    g_dist[e] = sqrtf(dx * dx + dy * dy + dz * dz);
}

// h = x @ emb_W + emb_b   (one node per block, 128 threads)
__global__ void embed_kernel(const float* __restrict__ x,
                             const float* __restrict__ W,
                             const float* __restrict__ b) {
    int n = blockIdx.x;
    int t = threadIdx.x;
    float acc = b[t];
#pragma unroll
    for (int k = 0; k < NODE_F; k++)
        acc = fmaf(x[n * NODE_F + k], W[k * HID + t], acc);
    g_h[n * HID + t] = acc;
}

__global__ void zero_agg_kernel() {
    int i = blockIdx.x * blockDim.x + threadIdx.x;
    if (i < N_NODES * HID) g_agg[i] = 0.f;
}
__global__ void zero_pool_kernel() {
    int i = blockIdx.x * blockDim.x + threadIdx.x;
    if (i < N_GRAPHS * HID) g_pool[i] = 0.f;
}

// ---------------------------------------------------------------------------
// Block-wide LayerNorm(+affine)+ReLU over the 128-column dimension.
// acc[EPB] lives per-thread (thread t holds column t for EPB rows).
// Result written to sOut[e][t] (stride 132). Ends with __syncthreads().
template <int EPB>
__device__ __forceinline__ void ln_relu_to_smem(float* acc,
                                                const float* __restrict__ g,
                                                const float* __restrict__ be,
                                                float (*sOut)[132],
                                                float (*sRed)[4][2],
                                                float (*sMV)[2],
                                                int tid) {
    int lane = tid & 31, warp = tid >> 5;
#pragma unroll
    for (int e = 0; e < EPB; e++) {
        float s = acc[e], s2 = acc[e] * acc[e];
#pragma unroll
        for (int o = 16; o > 0; o >>= 1) {
            s  += __shfl_xor_sync(0xffffffffu, s, o);
            s2 += __shfl_xor_sync(0xffffffffu, s2, o);
        }
        if (lane == 0) { sRed[e][warp][0] = s; sRed[e][warp][1] = s2; }
    }
    __syncthreads();
    if (tid < EPB) {
        float s = 0.f, s2 = 0.f;
#pragma unroll
        for (int w = 0; w < 4; w++) { s += sRed[tid][w][0]; s2 += sRed[tid][w][1]; }
        float mean = s * (1.0f / HID);
        float var  = s2 * (1.0f / HID) - mean * mean;
        var = fmaxf(var, 0.f);
        sMV[tid][0] = mean;
        sMV[tid][1] = rsqrtf(var + 1e-5f);
    }
    __syncthreads();
    float gg = g[tid], bb = be[tid];
#pragma unroll
    for (int e = 0; e < EPB; e++) {
        float v = fmaf((acc[e] - sMV[e][0]) * sMV[e][1], gg, bb);
        sOut[e][tid] = fmaxf(v, 0.f);
    }
    __syncthreads();
}

// ---------------------------------------------------------------------------
// Edge message kernel: 16 edges per block, 128 threads (thread = out column).
// m = relu(LN([h_dst, h_src, dist] @ W1 + b1)); m = relu(LN(m @ W2 + b2));
// agg[dst] += m  (atomic).
#define EPB_MSG 16
__global__ __launch_bounds__(128) void msg_kernel(
    const int* __restrict__ ei,
    const float* __restrict__ W1, const float* __restrict__ b1,
    const float* __restrict__ g1, const float* __restrict__ be1,
    const float* __restrict__ W2, const float* __restrict__ b2,
    const float* __restrict__ g2, const float* __restrict__ be2) {
    __shared__ __align__(16) float sIn[EPB_MSG][260];
    __shared__ __align__(16) float sM[EPB_MSG][132];
    __shared__ float sRed[EPB_MSG][4][2];
    __shared__ float sMV[EPB_MSG][2];
    __shared__ int sSrc[EPB_MSG], sDst[EPB_MSG];

    int tid = threadIdx.x;
    int e0 = blockIdx.x * EPB_MSG;  // E = 200000 = 12500 * 16 exactly

    if (tid < EPB_MSG) {
        sSrc[tid] = ei[e0 + tid];
        sDst[tid] = ei[N_EDGES + e0 + tid];
    }
    __syncthreads();
#pragma unroll
    for (int e = 0; e < EPB_MSG; e++) {
        sIn[e][tid]       = g_h[sDst[e] * HID + tid];
        sIn[e][HID + tid] = g_h[sSrc[e] * HID + tid];
    }
    if (tid < EPB_MSG) sIn[tid][256] = g_dist[e0 + tid];
    __syncthreads();

    float acc[EPB_MSG];
    // ---- MLP1: 257 -> 128 ----
    {
        float bv = b1[tid];
#pragma unroll
        for (int e = 0; e < EPB_MSG; e++) acc[e] = bv;
        for (int k4 = 0; k4 < 64; k4++) {
            const float* wp = W1 + (k4 * 4) * HID + tid;
            float w0 = wp[0], w1 = wp[HID], w2 = wp[2 * HID], w3 = wp[3 * HID];
#pragma unroll
            for (int e = 0; e < EPB_MSG; e++) {
                float4 v = *(const float4*)&sIn[e][k4 * 4];
                acc[e] = fmaf(v.x, w0, fmaf(v.y, w1, fmaf(v.z, w2, fmaf(v.w, w3, acc[e]))));
            }
        }
        float wd = W1[256 * HID + tid];
#pragma unroll
        for (int e = 0; e < EPB_MSG; e++) acc[e] = fmaf(sIn[e][256], wd, acc[e]);
    }
    ln_relu_to_smem<EPB_MSG>(acc, g1, be1, sM, sRed, sMV, tid);

    // ---- MLP2: 128 -> 128 ----
    {
        float bv = b2[tid];
#pragma unroll
        for (int e = 0; e < EPB_MSG; e++) acc[e] = bv;
        for (int k4 = 0; k4 < 32; k4++) {
            const float* wp = W2 + (k4 * 4) * HID + tid;
            float w0 = wp[0], w1 = wp[HID], w2 = wp[2 * HID], w3 = wp[3 * HID];
#pragma unroll
            for (int e = 0; e < EPB_MSG; e++) {
                float4 v = *(const float4*)&sM[e][k4 * 4];
                acc[e] = fmaf(v.x, w0, fmaf(v.y, w1, fmaf(v.z, w2, fmaf(v.w, w3, acc[e]))));
            }
        }
    }
    ln_relu_to_smem<EPB_MSG>(acc, g2, be2, sM, sRed, sMV, tid);

#pragma unroll
    for (int e = 0; e < EPB_MSG; e++)
        atomicAdd(&g_agg[sDst[e] * HID + tid], sM[e][tid]);
}

// ---------------------------------------------------------------------------
// Node update kernel: 8 nodes per block.
// u = relu(LN([h, agg] @ W1 + b1)); u = relu(LN(u @ W2 + b2)); h += u.
#define NPB 8
__global__ __launch_bounds__(128) void upd_kernel(
    const float* __restrict__ W1, const float* __restrict__ b1,
    const float* __restrict__ g1, const float* __restrict__ be1,
    const float* __restrict__ W2, const float* __restrict__ b2,
    const float* __restrict__ g2, const float* __restrict__ be2) {
    __shared__ __align__(16) float sIn[NPB][256];
    __shared__ __align__(16) float sM[NPB][132];
    __shared__ float sRed[NPB][4][2];
    __shared__ float sMV[NPB][2];

    int tid = threadIdx.x;
    int n0 = blockIdx.x * NPB;  // 25000 = 3125 * 8 exactly

#pragma unroll
    for (int e = 0; e < NPB; e++) {
        sIn[e][tid]       = g_h[(n0 + e) * HID + tid];
        sIn[e][HID + tid] = g_agg[(n0 + e) * HID + tid];
    }
    __syncthreads();

    float acc[NPB];
    {
        float bv = b1[tid];
#pragma unroll
        for (int e = 0; e < NPB; e++) acc[e] = bv;
        for (int k4 = 0; k4 < 64; k4++) {
            const float* wp = W1 + (k4 * 4) * HID + tid;
            float w0 = wp[0], w1 = wp[HID], w2 = wp[2 * HID], w3 = wp[3 * HID];
#pragma unroll
            for (int e = 0; e < NPB; e++) {
                float4 v = *(const float4*)&sIn[e][k4 * 4];
                acc[e] = fmaf(v.x, w0, fmaf(v.y, w1, fmaf(v.z, w2, fmaf(v.w, w3, acc[e]))));
            }
        }
    }
    ln_relu_to_smem<NPB>(acc, g1, be1, sM, sRed, sMV, tid);
    {
        float bv = b2[tid];
#pragma unroll
        for (int e = 0; e < NPB; e++) acc[e] = bv;
        for (int k4 = 0; k4 < 32; k4++) {
            const float* wp = W2 + (k4 * 4) * HID + tid;
            float w0 = wp[0], w1 = wp[HID], w2 = wp[2 * HID], w3 = wp[3 * HID];
#pragma unroll
            for (int e = 0; e < NPB; e++) {
                float4 v = *(const float4*)&sM[e][k4 * 4];
                acc[e] = fmaf(v.x, w0, fmaf(v.y, w1, fmaf(v.z, w2, fmaf(v.w, w3, acc[e]))));
            }
        }
    }
    ln_relu_to_smem<NPB>(acc, g2, be2, sM, sRed, sMV, tid);

#pragma unroll
    for (int e = 0; e < NPB; e++)
        g_h[(n0 + e) * HID + tid] += sM[e][tid];
}

// ---------------------------------------------------------------------------
__global__ void pool_kernel(const int* __restrict__ batch) {
    int n = blockIdx.x;
    int t = threadIdx.x;
    atomicAdd(&g_pool[batch[n] * HID + t], g_h[n * HID + t]);
}

// out[g] = relu(pool[g] @ W1 + b1) @ W2 + b2
__global__ void pred_kernel(const float* __restrict__ W1, const float* __restrict__ b1,
                            const float* __restrict__ W2, const float* __restrict__ b2,
                            float* __restrict__ out) {
    __shared__ float sred[128];
    int g = blockIdx.x;
    int t = threadIdx.x;
    float acc = b1[t];
    for (int k = 0; k < HID; k++)
        acc = fmaf(g_pool[g * HID + k], W1[k * HID + t], acc);
    acc = fmaxf(acc, 0.f) * W2[t];
    sred[t] = acc;
    __syncthreads();
    for (int o = 64; o > 0; o >>= 1) {
        if (t < o) sred[t] += sred[t + o];
        __syncthreads();
    }
    if (t == 0) out[g] = sred[0] + b2[0];
}

// ---------------------------------------------------------------------------
extern "C" void kernel_launch(void* const* d_in, const int* in_sizes, int n_in,
                              void* d_out, int out_size) {
    const float* x     = (const float*)d_in[0];
    const float* pos   = (const float*)d_in[1];
    const int*   ei    = (const int*)d_in[2];
    const int*   batch = (const int*)d_in[3];
    const float* emb_W = (const float*)d_in[4];
    const float* emb_b = (const float*)d_in[5];

    const float *mW1, *mb1, *mg1, *mbe1, *mW2, *mb2, *mg2, *mbe2;
    const float *uW1, *ub1, *ug1, *ube1, *uW2, *ub2, *ug2, *ube2;

    if (in_sizes[8] == 81920) {
        // setup_inputs dict-insertion order: W1,b1,W2,b2 (msg), W1,b1,W2,b2 (upd), then g/be
        mW1  = (const float*)d_in[6];  mb1  = (const float*)d_in[7];
        mW2  = (const float*)d_in[8];  mb2  = (const float*)d_in[9];
        uW1  = (const float*)d_in[10]; ub1  = (const float*)d_in[11];
        uW2  = (const float*)d_in[12]; ub2  = (const float*)d_in[13];
        mg1  = (const float*)d_in[14]; mbe1 = (const float*)d_in[15];
        mg2  = (const float*)d_in[16]; mbe2 = (const float*)d_in[17];
        ug1  = (const float*)d_in[18]; ube1 = (const float*)d_in[19];
        ug2  = (const float*)d_in[20]; ube2 = (const float*)d_in[21];
    } else {
        // reference() signature order: g/be interleaved
        mW1  = (const float*)d_in[6];  mb1  = (const float*)d_in[7];
        mg1  = (const float*)d_in[8];  mbe1 = (const float*)d_in[9];
        mW2  = (const float*)d_in[10]; mb2  = (const float*)d_in[11];
        mg2  = (const float*)d_in[12]; mbe2 = (const float*)d_in[13];
        uW1  = (const float*)d_in[14]; ub1  = (const float*)d_in[15];
        ug1  = (const float*)d_in[16]; ube1 = (const float*)d_in[17];
        uW2  = (const float*)d_in[18]; ub2  = (const float*)d_in[19];
        ug2  = (const float*)d_in[20]; ube2 = (const float*)d_in[21];
    }
    const float* pW1 = (const float*)d_in[22];
    const float* pb1 = (const float*)d_in[23];
    const float* pW2 = (const float*)d_in[24];
    const float* pb2 = (const float*)d_in[25];
    float* out = (float*)d_out;

    dist_kernel<<<(N_EDGES + 255) / 256, 256>>>(pos, ei);
    embed_kernel<<<N_NODES, 128>>>(x, emb_W, emb_b);

    for (int l = 0; l < DEPTH; l++) {
        zero_agg_kernel<<<(N_NODES * HID + 255) / 256, 256>>>();
        msg_kernel<<<N_EDGES / EPB_MSG, 128>>>(
            ei,
            mW1 + l * 257 * HID, mb1 + l * HID, mg1 + l * HID, mbe1 + l * HID,
            mW2 + l * HID * HID, mb2 + l * HID, mg2 + l * HID, mbe2 + l * HID);
        upd_kernel<<<N_NODES / NPB, 128>>>(
            uW1 + l * 256 * HID, ub1 + l * HID, ug1 + l * HID, ube1 + l * HID,
            uW2 + l * HID * HID, ub2 + l * HID, ug2 + l * HID, ube2 + l * HID);
    }

    zero_pool_kernel<<<(N_GRAPHS * HID + 255) / 256, 256>>>();
    pool_kernel<<<N_NODES, 128>>>(batch);
    pred_kernel<<<N_GRAPHS, 128>>>(pW1, pb1, pW2, pb2, out);
}